// round 17
// baseline (speedup 1.0000x reference)
#include <cuda_runtime.h>
#include <cuda_fp16.h>
#include <math.h>
#include <stdint.h>

#define BATCH   8
#define S_LEN   1024
#define DM      1024
#define HEADS   16
#define DK      64
#define M_ROWS  (BATCH * S_LEN)   // 8192

typedef __half h16;

// ------------------------- device scratch (no allocs allowed) ---------------
__device__ h16 g_A3 [3 * M_ROWS * DM];
__device__ h16 g_Qsg[M_ROWS * DM];
__device__ h16 g_Ksg[M_ROWS * DM];
__device__ h16 g_Vsg[M_ROWS * DM];
__device__ h16 g_Osg[M_ROWS * DM];
__device__ h16 g_Whi[4 * DM * DM];

// ------------------------- helpers -----------------------------------------
__device__ __forceinline__ uint32_t smem_u32(const void* p) {
    return (uint32_t)__cvta_generic_to_shared(p);
}
__device__ __forceinline__ void cpa16(uint32_t smem_addr, const void* g) {
    asm volatile("cp.async.cg.shared.global [%0], [%1], 16;" :: "r"(smem_addr), "l"(g));
}
__device__ __forceinline__ float ex2(float x) {
    float r;
    asm("ex2.approx.f32 %0, %1;" : "=f"(r) : "f"(x));
    return r;
}
__device__ __forceinline__ uint32_t pack2h(float lo, float hi) {
    uint32_t r;
    asm("cvt.rn.f16x2.f32 %0, %1, %2;" : "=r"(r) : "f"(hi), "f"(lo));
    return r;
}

#define LDSM4(r, addr) \
    asm volatile("ldmatrix.sync.aligned.m8n8.x4.shared.b16 {%0,%1,%2,%3}, [%4];" \
        : "=r"((r)[0]), "=r"((r)[1]), "=r"((r)[2]), "=r"((r)[3]) : "r"(addr))

#define LDSM4T(r, addr) \
    asm volatile("ldmatrix.sync.aligned.m8n8.x4.trans.shared.b16 {%0,%1,%2,%3}, [%4];" \
        : "=r"((r)[0]), "=r"((r)[1]), "=r"((r)[2]), "=r"((r)[3]) : "r"(addr))

#define MMAF16(d, a, b0, b1) \
    asm volatile("mma.sync.aligned.m16n8k16.row.col.f32.f16.f16.f32 " \
        "{%0,%1,%2,%3}, {%4,%5,%6,%7}, {%8,%9}, {%0,%1,%2,%3};" \
        : "+f"((d)[0]), "+f"((d)[1]), "+f"((d)[2]), "+f"((d)[3]) \
        : "r"((a)[0]), "r"((a)[1]), "r"((a)[2]), "r"((a)[3]), "r"(b0), "r"(b1))

// ------------------------- GEMM config (KSTEP=64, 3-stage ring) -------------
#define KSTEP     64
#define NKI       (DM / KSTEP)        // 16
#define ROW_B     144                 // 128B payload + 16 pad (conflict-free ldsm)
#define REGION_B  (128 * ROW_B)       // 18432
#define PSTAGE_B  (2 * REGION_B)      // 36864 (A, W)
#define GEMM_SMEM (3 * PSTAGE_B)      // 110592 (3-stage ring)

// ------------------------- single-term fp16 GEMM ----------------------------
// MODE 0 (out-proj): z=0 only, A = Osg, W slice 3, f32 C output.
// MODE 1 (qkv proj): z in {0,1,2}, A = A3 slice z, W slice z, fp16 output.
template<int MODE>
__global__ __launch_bounds__(256, 2)
void gemm_h1(const h16* __restrict__ Abase, const h16* __restrict__ Wh,
             const float* __restrict__ b0p, const float* __restrict__ b1p,
             const float* __restrict__ b2p,
             float* __restrict__ C,
             h16* __restrict__ Qs, h16* __restrict__ Ks, h16* __restrict__ Vs)
{
    extern __shared__ char smc[];
    const uint32_t sbase = smem_u32(smc);
    const int z = blockIdx.z;
    const h16* Az = Abase + (MODE == 1 ? (size_t)z * M_ROWS * DM : 0);
    const h16* Wz = Wh + (size_t)(MODE == 1 ? z : 3) * DM * DM;
    const float* bias = (z == 0) ? b0p : (z == 1) ? b1p : b2p;
    h16* Oz = (z == 0) ? Qs : (z == 1) ? Ks : Vs;

    const int tid  = threadIdx.x;
    const int wid  = tid >> 5;
    const int lane = tid & 31;
    const int M0 = (wid & 3) * 32;
    const int N0 = (wid >> 2) * 64;
    const int aRow0 = blockIdx.y * 128;
    const int bRow0 = blockIdx.x * 128;

    const int la_row = (lane & 7) + ((lane >> 3) & 1) * 8;
    const int la_k   = (lane >> 4) * 8;
    const uint32_t aoff = (uint32_t)((M0 + la_row) * ROW_B + la_k * 2);
    const int lb_row = ((lane >> 4) * 8) + (lane & 7);
    const int lb_k   = ((lane >> 3) & 1) * 8;
    const uint32_t boff = (uint32_t)((N0 + lb_row) * ROW_B + lb_k * 2);

    // loader: per region 128 rows x 8 chunks(16B) = 1024 chunks; thread does 4
    const int lrow = tid >> 3;           // 0..31 (x4 passes of 32 rows)
    const int lch  = tid & 7;
    const uint32_t lsoff = (uint32_t)(lrow * ROW_B + lch * 16);

    float acc[2][8][4];
    #pragma unroll
    for (int i = 0; i < 2; i++)
        #pragma unroll
        for (int j = 0; j < 8; j++)
            #pragma unroll
            for (int v = 0; v < 4; v++) acc[i][j][v] = 0.f;

    #pragma unroll
    for (int s = 0; s < 2; s++) {
        const uint32_t stg = sbase + s * PSTAGE_B;
        const uint32_t kc = s * KSTEP + lch * 8;
        #pragma unroll
        for (int qt = 0; qt < 4; qt++) {
            const int r = lrow + qt * 32;
            const uint32_t so = lsoff + (uint32_t)(qt * 32 * ROW_B);
            cpa16(stg + so,            Az + (size_t)(aRow0 + r) * DM + kc);
            cpa16(stg + REGION_B + so, Wz + (size_t)(bRow0 + r) * DM + kc);
        }
        asm volatile("cp.async.commit_group;" ::: "memory");
    }

    for (int kt = 0; kt < NKI; kt++) {
        int slot = kt % 3;
        const uint32_t stg = sbase + (uint32_t)slot * PSTAGE_B;

        if (kt < NKI - 1) asm volatile("cp.async.wait_group 1;" ::: "memory");
        else              asm volatile("cp.async.wait_group 0;" ::: "memory");
        __syncthreads();   // single barrier; prefetch below targets slot freed last iter

        #pragma unroll
        for (int kk2 = 0; kk2 < 4; kk2++) {
            uint32_t ah[2][4];
            LDSM4(ah[0], stg + aoff + kk2 * 32);
            LDSM4(ah[1], stg + aoff + kk2 * 32 + 16 * ROW_B);
            #pragma unroll
            for (int np = 0; np < 4; np++) {
                uint32_t bh[4];
                LDSM4(bh, stg + REGION_B + boff + np * 16 * ROW_B + kk2 * 32);
                #pragma unroll
                for (int mf = 0; mf < 2; mf++) {
                    MMAF16(acc[mf][np * 2 + 0], ah[mf], bh[0], bh[1]);
                    MMAF16(acc[mf][np * 2 + 1], ah[mf], bh[2], bh[3]);
                }
            }
        }

        if (kt + 2 < NKI) {
            int ns = slot + 2; if (ns >= 3) ns -= 3;   // slot consumed at iter kt-1
            const uint32_t nsb = sbase + (uint32_t)ns * PSTAGE_B;
            const uint32_t kc = (kt + 2) * KSTEP + lch * 8;
            #pragma unroll
            for (int qt = 0; qt < 4; qt++) {
                const int r = lrow + qt * 32;
                const uint32_t so = lsoff + (uint32_t)(qt * 32 * ROW_B);
                cpa16(nsb + so,            Az + (size_t)(aRow0 + r) * DM + kc);
                cpa16(nsb + REGION_B + so, Wz + (size_t)(bRow0 + r) * DM + kc);
            }
            asm volatile("cp.async.commit_group;" ::: "memory");
        }
    }

    #pragma unroll
    for (int mf = 0; mf < 2; mf++) {
        const int row = aRow0 + M0 + mf * 16 + (lane >> 2);
        #pragma unroll
        for (int nf = 0; nf < 8; nf++) {
            const int col = bRow0 + N0 + nf * 8 + (lane & 3) * 2;
            const float b0 = bias[col], b1 = bias[col + 1];
            float f0 = acc[mf][nf][0] + b0, f1 = acc[mf][nf][1] + b1;
            float f2 = acc[mf][nf][2] + b0, f3 = acc[mf][nf][3] + b1;
            if (MODE == 0) {
                *(float2*)(C + (size_t)row * DM + col)       = make_float2(f0, f1);
                *(float2*)(C + (size_t)(row + 8) * DM + col) = make_float2(f2, f3);
            } else {
                *(uint32_t*)(Oz + (size_t)row * DM + col)       = pack2h(f0, f1);
                *(uint32_t*)(Oz + (size_t)(row + 8) * DM + col) = pack2h(f2, f3);
            }
        }
    }
}

// ------------------------- activation rounding (3 inputs batched) ----------
__global__ __launch_bounds__(256)
void conv_act3(const float4* __restrict__ in0, const float4* __restrict__ in1,
               const float4* __restrict__ in2, h16* __restrict__ out, int n4)
{
    int i = blockIdx.x * 256 + threadIdx.x;
    if (i >= n4) return;
    const int y = blockIdx.y;
    const float4* in = (y == 0) ? in0 : (y == 1) ? in1 : in2;
    float4 v = in[i];
    uint2 r = make_uint2(pack2h(v.x, v.y), pack2h(v.z, v.w));
    *(uint2*)(out + (size_t)y * (size_t)n4 * 4 + (size_t)i * 4) = r;
}

// ------------------------- weight transpose (4 batched, single fp16) --------
__global__ __launch_bounds__(256)
void transpose_w4(const float* __restrict__ W0, const float* __restrict__ W1,
                  const float* __restrict__ W2, const float* __restrict__ W3,
                  h16* __restrict__ hi)
{
    __shared__ float t[32][33];
    const int z = blockIdx.z;
    const float* W = (z == 0) ? W0 : (z == 1) ? W1 : (z == 2) ? W2 : W3;
    const size_t zofs = (size_t)z * DM * DM;
    const int n0 = blockIdx.x * 32;
    const int k0 = blockIdx.y * 32;
    const int tx = threadIdx.x & 31;
    const int ty = threadIdx.x >> 5;
    #pragma unroll
    for (int r = ty; r < 32; r += 8)
        t[r][tx] = W[(size_t)(k0 + r) * DM + n0 + tx];
    __syncthreads();
    #pragma unroll
    for (int r = ty; r < 32; r += 8)
        hi[zofs + (size_t)(n0 + r) * DM + k0 + tx] = __float2half_rn(t[tx][r]);
}

// ------------------------- flash attention (fp16, all 1-term, Br=128) -------
#define FROW   144
#define FREG   (64 * FROW)            // 9216
#define FSTAGE (2 * FREG + 256)       // 18688 (K, V, mask)
#define FLASH_SMEM (2 * FSTAGE)       // 37376
#define NT     (S_LEN / 64)           // 16

__device__ __forceinline__ void load_kv_stage(
    uint32_t stg, const h16* __restrict__ Ksg, const h16* __restrict__ Vsg,
    const int* __restrict__ mask, int b, int hcol, int k0, int tid)
{
    #pragma unroll
    for (int i = 0; i < 2; i++) {
        const int c = tid + 256 * i;
        const int r = c >> 3;
        const int cc = c & 7;
        const uint32_t so = (uint32_t)(r * FROW + cc * 16);
        const size_t g = (size_t)(b * S_LEN + k0 + r) * DM + hcol + cc * 8;
        cpa16(stg + so,        Ksg + g);
        cpa16(stg + FREG + so, Vsg + g);
    }
    if (tid < 16)
        cpa16(stg + 2 * FREG + tid * 16, mask + b * S_LEN + k0 + tid * 4);
}

__global__ __launch_bounds__(256, 2)
void flash_attn_tc(const h16* __restrict__ Qsg,
                   const h16* __restrict__ Ksg, const h16* __restrict__ Vsg,
                   const int* __restrict__ mask,
                   h16* __restrict__ Osg)
{
    extern __shared__ char smf[];
    const uint32_t base = smem_u32(smf);
    const int tid  = threadIdx.x;
    const int wid  = tid >> 5;
    const int lane = tid & 31;
    const int b  = blockIdx.z;
    const int h  = blockIdx.y;
    const int q0 = blockIdx.x * 128;
    const int hcol = h * DK;

    // ---- stage Q (single, 128 rows x 8 chunks = 1024 chunks) ----
    #pragma unroll
    for (int i = 0; i < 4; i++) {
        const int c = tid + 256 * i;
        const int r = c >> 3;
        const int cc = c & 7;
        const uint32_t so = (uint32_t)(r * FROW + cc * 16);
        const size_t g = (size_t)(b * S_LEN + q0 + r) * DM + hcol + cc * 8;
        cpa16(base + so, Qsg + g);
    }
    asm volatile("cp.async.commit_group;" ::: "memory");
    asm volatile("cp.async.wait_group 0;" ::: "memory");
    __syncthreads();

    const int la_row = (lane & 7) + ((lane >> 3) & 1) * 8;
    const int la_k   = (lane >> 4) * 8;
    uint32_t qh[4][4];
    {
        const uint32_t qaddr = base + (uint32_t)((wid * 16 + la_row) * FROW + la_k * 2);
        #pragma unroll
        for (int kf = 0; kf < 4; kf++)
            LDSM4(qh[kf], qaddr + kf * 32);
    }
    __syncthreads();

    load_kv_stage(base,          Ksg, Vsg, mask, b, hcol, 0,  tid);
    asm volatile("cp.async.commit_group;" ::: "memory");
    load_kv_stage(base + FSTAGE, Ksg, Vsg, mask, b, hcol, 64, tid);
    asm volatile("cp.async.commit_group;" ::: "memory");

    const int lb_row = ((lane >> 4) * 8) + (lane & 7);
    const int lb_k   = ((lane >> 3) & 1) * 8;
    const int vb_row = (lane & 7) + ((lane >> 3) & 1) * 8;
    const int vb_col = (lane >> 4) * 8;

    float l2[2] = {0.f, 0.f};
    float oacc[4][8];
    #pragma unroll
    for (int i = 0; i < 4; i++)
        #pragma unroll
        for (int j = 0; j < 8; j++) oacc[i][j] = 0.f;

    const float C1   = 0.04508422f;          // log2(e)/32
    const float MNEG = -1e20f * 0.04508422f;

    for (int t = 0; t < NT; t++) {
        const uint32_t stg = base + (uint32_t)(t & 1) * FSTAGE;

        if (t == NT - 1) asm volatile("cp.async.wait_group 0;" ::: "memory");
        else             asm volatile("cp.async.wait_group 1;" ::: "memory");
        __syncthreads();

        // ---- S = Q K^T (1-term) ----
        float sacc[4][8];
        #pragma unroll
        for (int np = 0; np < 4; np++)
            #pragma unroll
            for (int j = 0; j < 8; j++) sacc[np][j] = 0.f;

        #pragma unroll
        for (int np = 0; np < 4; np++) {
            const uint32_t kb = stg + (uint32_t)((np * 16 + lb_row) * FROW + lb_k * 2);
            float* d0 = &sacc[np][0];
            float* d1 = &sacc[np][4];
            #pragma unroll
            for (int kf = 0; kf < 4; kf++) {
                uint32_t kh[4];
                LDSM4(kh, kb + kf * 32);
                MMAF16(d0, qh[kf], kh[0], kh[1]);
                MMAF16(d1, qh[kf], kh[2], kh[3]);
            }
        }

        // ---- mask + scale + P = exp2; pack P to fp16 single ----
        const char* mbase = smf + (t & 1) * FSTAGE + 2 * FREG;
        uint32_t phi[4][4];
        #pragma unroll
        for (int np = 0; np < 4; np++) {
            #pragma unroll
            for (int h2 = 0; h2 < 2; h2++) {
                const int col = np * 16 + h2 * 8 + 2 * (lane & 3);
                int2 mv = *(const int2*)(mbase + col * 4);
                float* d = &sacc[np][h2 * 4];
                d[0] = ex2(mv.x ? d[0] * C1 : MNEG);
                d[1] = ex2(mv.y ? d[1] * C1 : MNEG);
                d[2] = ex2(mv.x ? d[2] * C1 : MNEG);
                d[3] = ex2(mv.y ? d[3] * C1 : MNEG);
                l2[0] += d[0] + d[1];
                l2[1] += d[2] + d[3];
                phi[np][h2 * 2 + 0] = pack2h(d[0], d[1]);
                phi[np][h2 * 2 + 1] = pack2h(d[2], d[3]);
            }
        }

        // ---- O += P V (1-term) ----
        #pragma unroll
        for (int npd = 0; npd < 4; npd++) {
            float* o0 = &oacc[npd][0];
            float* o1 = &oacc[npd][4];
            #pragma unroll
            for (int kf = 0; kf < 4; kf++) {
                const uint32_t va = stg + FREG +
                    (uint32_t)((kf * 16 + vb_row) * FROW + (npd * 16 + vb_col) * 2);
                uint32_t vh[4];
                LDSM4T(vh, va);
                MMAF16(o0, phi[kf], vh[0], vh[1]);
                MMAF16(o1, phi[kf], vh[2], vh[3]);
            }
        }

        __syncthreads();
        if (t + 2 < NT) {
            load_kv_stage(stg, Ksg, Vsg, mask, b, hcol, (t + 2) * 64, tid);
            asm volatile("cp.async.commit_group;" ::: "memory");
        }
    }

    // ---- l reduction + finalize (single fp16 out) ----
    l2[0] += __shfl_xor_sync(0xffffffffu, l2[0], 1);
    l2[0] += __shfl_xor_sync(0xffffffffu, l2[0], 2);
    l2[1] += __shfl_xor_sync(0xffffffffu, l2[1], 1);
    l2[1] += __shfl_xor_sync(0xffffffffu, l2[1], 2);

    const float inv0 = 1.f / l2[0];
    const float inv1 = 1.f / l2[1];
    const int r0 = q0 + wid * 16 + (lane >> 2);
    const size_t row0 = (size_t)(b * S_LEN + r0) * DM + hcol;
    const size_t row1 = row0 + 8 * DM;
    #pragma unroll
    for (int npd = 0; npd < 4; npd++) {
        #pragma unroll
        for (int h2 = 0; h2 < 2; h2++) {
            const int c = npd * 16 + h2 * 8 + 2 * (lane & 3);
            float* d = &oacc[npd][h2 * 4];
            *(uint32_t*)(Osg + row0 + c) = pack2h(d[0] * inv0, d[1] * inv0);
            *(uint32_t*)(Osg + row1 + c) = pack2h(d[2] * inv1, d[3] * inv1);
        }
    }
}

// ---------------------------------------------------------------------------
extern "C" void kernel_launch(void* const* d_in, const int* in_sizes, int n_in,
                              void* d_out, int out_size)
{
    const float* values = (const float*)d_in[0];
    const float* keys   = (const float*)d_in[1];
    const float* query  = (const float*)d_in[2];
    const int*   mask   = (const int*)  d_in[3];
    const float* Wq = (const float*)d_in[4];
    const float* bq = (const float*)d_in[5];
    const float* Wk = (const float*)d_in[6];
    const float* bk = (const float*)d_in[7];
    const float* Wv = (const float*)d_in[8];
    const float* bv = (const float*)d_in[9];
    const float* Wo = (const float*)d_in[10];
    const float* bo = (const float*)d_in[11];
    float* out = (float*)d_out;

    h16 *A3, *Qsg, *Ksg, *Vsg, *Osg, *Whi;
    cudaGetSymbolAddress((void**)&A3,  g_A3);
    cudaGetSymbolAddress((void**)&Qsg, g_Qsg);
    cudaGetSymbolAddress((void**)&Ksg, g_Ksg);
    cudaGetSymbolAddress((void**)&Vsg, g_Vsg);
    cudaGetSymbolAddress((void**)&Osg, g_Osg);
    cudaGetSymbolAddress((void**)&Whi, g_Whi);

    cudaFuncSetAttribute(gemm_h1<0>, cudaFuncAttributeMaxDynamicSharedMemorySize, GEMM_SMEM);
    cudaFuncSetAttribute(gemm_h1<1>, cudaFuncAttributeMaxDynamicSharedMemorySize, GEMM_SMEM);
    cudaFuncSetAttribute(flash_attn_tc, cudaFuncAttributeMaxDynamicSharedMemorySize, FLASH_SMEM);

    const size_t SZ = (size_t)M_ROWS * DM;
    const int n4 = (int)(SZ / 4);

    transpose_w4<<<dim3(DM / 32, DM / 32, 4), 256>>>(Wq, Wk, Wv, Wo, Whi);

    conv_act3<<<dim3(n4 / 256, 3), 256>>>((const float4*)query, (const float4*)keys,
                                          (const float4*)values, A3, n4);

    gemm_h1<1><<<dim3(DM / 128, M_ROWS / 128, 3), 256, GEMM_SMEM>>>(
        A3, Whi, bq, bk, bv, nullptr, Qsg, Ksg, Vsg);

    dim3 gattn(S_LEN / 128, HEADS, BATCH);   // (8, 16, 8) = 1024 CTAs
    flash_attn_tc<<<gattn, 256, FLASH_SMEM>>>(Qsg, Ksg, Vsg, mask, Osg);

    gemm_h1<0><<<dim3(DM / 128, M_ROWS / 128, 1), 256, GEMM_SMEM>>>(
        Osg, Whi, bo, nullptr, nullptr, out, nullptr, nullptr, nullptr);
}